// round 15
// baseline (speedup 1.0000x reference)
#include <cuda_runtime.h>
#include <cuda_fp16.h>
#include <cstddef>
#include <cstdint>

#define BATCH   64
#define NCAPS   32
#define NROUTES 2048
#define INDIM   16
#define OUTDIM  32
#define NITERS  3
#define NWARPS  16

typedef unsigned long long u64;
#define FMA2(d, a, b, c) \
    asm("fma.rn.f32x2 %0, %1, %2, %3;" : "=l"(d) : "l"(a), "l"(b), "l"(c))
#define PACKF2(o, lo, hi) \
    asm("mov.b64 %0, {%1, %2};" : "=l"(o) : "f"(lo), "f"(hi))
#define UNPACKF2(lo, hi, in) \
    asm("mov.b64 {%0, %1}, %2;" : "=f"(lo), "=f"(hi) : "l"(in))

// Global fp16 prior buffer (static device scratch).
// half2 layout: pri[c][bp][n][b1][oh], oh = o/2 (16 half2 per (n,b1))
__device__ __half2 g_pri[(size_t)NCAPS * 32 * NROUTES * 2 * 16];

// ================= K1: priors GEMM — barrier-free, no SMEM =================
// 512 threads: thread = (route rl=t>>4 in 0..31, half2-col og2=t&15).
// W k-packed once into 16 u64 regs; x read directly via __ldg (L1 broadcast:
// all 16 og2 lanes load the same 16B). One flat 64-batch loop, zero barriers.
__global__ void __launch_bounds__(512, 2)
caps_k1_priors(const float* __restrict__ x, const float* __restrict__ W)
{
    const int t   = threadIdx.x;
    const int rl  = t >> 4;          // 0..31
    const int og2 = t & 15;          // 0..15 (half2 column)
    const int c   = blockIdx.x >> 6;
    const int r0  = (blockIdx.x & 63) * 32;
    const int n   = r0 + rl;

    // W k-pair transpose into registers:
    //   wpA[j] = {W[2j][2og2],   W[2j+1][2og2]}
    //   wpB[j] = {W[2j][2og2+1], W[2j+1][2og2+1]}
    u64 wpA[8], wpB[8];
    {
        const u64* Wp = reinterpret_cast<const u64*>(W)
                      + ((size_t)(c * NROUTES + n) * INDIM) * 16 + og2;
#pragma unroll
        for (int jj = 0; jj < 4; jj++) {
            u64 v0 = __ldg(Wp + (4 * jj + 0) * 16);
            u64 v1 = __ldg(Wp + (4 * jj + 1) * 16);
            u64 v2 = __ldg(Wp + (4 * jj + 2) * 16);
            u64 v3 = __ldg(Wp + (4 * jj + 3) * 16);
            float l0, h0, l1, h1, l2, h2, l3, h3;
            UNPACKF2(l0, h0, v0); UNPACKF2(l1, h1, v1);
            UNPACKF2(l2, h2, v2); UNPACKF2(l3, h3, v3);
            PACKF2(wpA[2 * jj],     l0, l1); PACKF2(wpB[2 * jj],     h0, h1);
            PACKF2(wpA[2 * jj + 1], l2, l3); PACKF2(wpB[2 * jj + 1], h2, h3);
        }
    }

    // x row base for (b=0, n): ulonglong2 units (16 B); stride per b = 2048*4
    const ulonglong2* xb = reinterpret_cast<const ulonglong2*>(x) + (size_t)n * 4;
    const size_t bstride = (size_t)NROUTES * 4;

    const size_t obase = (((size_t)c * 32) * NROUTES + n) * 2 * 16 + og2;
    // off(b) = obase + (b>>1)*(NROUTES*2*16) + (b&1)*16

#pragma unroll 2
    for (int b = 0; b < BATCH; b++) {
        const ulonglong2* xr = xb + (size_t)b * bstride;
        ulonglong2 x0 = __ldg(xr + 0);
        ulonglong2 x1 = __ldg(xr + 1);
        ulonglong2 x2 = __ldg(xr + 2);
        ulonglong2 x3 = __ldg(xr + 3);

        u64 accA = 0ull, accB = 0ull;   // {+0.f,+0.f}
        FMA2(accA, x0.x, wpA[0], accA); FMA2(accB, x0.x, wpB[0], accB);
        FMA2(accA, x0.y, wpA[1], accA); FMA2(accB, x0.y, wpB[1], accB);
        FMA2(accA, x1.x, wpA[2], accA); FMA2(accB, x1.x, wpB[2], accB);
        FMA2(accA, x1.y, wpA[3], accA); FMA2(accB, x1.y, wpB[3], accB);
        FMA2(accA, x2.x, wpA[4], accA); FMA2(accB, x2.x, wpB[4], accB);
        FMA2(accA, x2.y, wpA[5], accA); FMA2(accB, x2.y, wpB[5], accB);
        FMA2(accA, x3.x, wpA[6], accA); FMA2(accB, x3.x, wpB[6], accB);
        FMA2(accA, x3.y, wpA[7], accA); FMA2(accB, x3.y, wpB[7], accB);

        float a0l, a0h, a1l, a1h;
        UNPACKF2(a0l, a0h, accA);
        UNPACKF2(a1l, a1h, accB);
        float a0 = a0l + a0h;           // col 2og2   (even-k + odd-k)
        float a1 = a1l + a1h;           // col 2og2+1

        size_t off = obase + (size_t)(b >> 1) * (NROUTES * 2 * 16) + (size_t)(b & 1) * 16;
        g_pri[off] = __floats2half2_rn(a0, a1);
    }
}

// ================= K2: routing (1 batch per CTA, 2 CTAs/SM) =================
#define SPH 17
#define K2_SP_HALF2S (1024 * SPH)
#define K2_NSCR (32 + 32 + 16 + NWARPS * 32 + 4)
#define K2_SMEM_BYTES ((K2_SP_HALF2S + K2_NSCR) * 4)   // 72016

__global__ void __launch_bounds__(512, 2)
caps_k2_route(float* __restrict__ out)
{
    extern __shared__ __half2 smh[];
    __half2* sp  = smh;
    float* scr  = reinterpret_cast<float*>(smh + K2_SP_HALF2S);
    float* Vsh  = scr;                       // 32
    float* sred = scr + 32;                  // 32
    float* wred = scr + 64;                  // 16
    float* wvec = scr + 80;                  // 16*32
    float* scal = scr + 80 + NWARPS * 32;    // 4

    const int t    = threadIdx.x;
    const int lane = t & 31;
    const int wid  = t >> 5;
    const int b1   = blockIdx.x & 1;
    const int bp   = (blockIdx.x >> 1) & 31;
    const int c    = blockIdx.x >> 6;
    const int b    = bp * 2 + b1;

    const float4* P4 = reinterpret_cast<const float4*>(
        g_pri + (((size_t)c * 32 + bp) * NROUTES) * 32);

    // ---- pass 1: routes 1024..2047 -> sp rows 0..1023 (4-deep MLP batches) ----
#pragma unroll
    for (int kk = 0; kk < 2; kk++) {
        float4 v[4];
#pragma unroll
        for (int u = 0; u < 4; u++) {
            int idx = t + (kk * 4 + u) * 512;
            int nl = idx >> 2, q = idx & 3;
            v[u] = __ldg(P4 + (size_t)(1024 + nl) * 8 + b1 * 4 + q);
        }
#pragma unroll
        for (int u = 0; u < 4; u++) {
            int idx = t + (kk * 4 + u) * 512;
            int nl = idx >> 2, q = idx & 3;
            const __half2* h = reinterpret_cast<const __half2*>(&v[u]);
            __half2* dst = sp + (size_t)nl * SPH + q * 4;
            dst[0] = h[0]; dst[1] = h[1]; dst[2] = h[2]; dst[3] = h[3];
        }
    }
    __syncthreads();

    __half2 A[16], B[16];
    {
        const __half2* pA = sp + (size_t)t * SPH;
        const __half2* pB = sp + (size_t)(512 + t) * SPH;
#pragma unroll
        for (int j = 0; j < 16; j++) { A[j] = pA[j]; B[j] = pB[j]; }
    }
    __syncthreads();

    // ---- pass 2: routes 0..1023 -> sp rows (4-deep MLP batches) ----
#pragma unroll
    for (int kk = 0; kk < 2; kk++) {
        float4 v[4];
#pragma unroll
        for (int u = 0; u < 4; u++) {
            int idx = t + (kk * 4 + u) * 512;
            int nl = idx >> 2, q = idx & 3;
            v[u] = __ldg(P4 + (size_t)nl * 8 + b1 * 4 + q);
        }
#pragma unroll
        for (int u = 0; u < 4; u++) {
            int idx = t + (kk * 4 + u) * 512;
            int nl = idx >> 2, q = idx & 3;
            const __half2* h = reinterpret_cast<const __half2*>(&v[u]);
            __half2* dst = sp + (size_t)nl * SPH + q * 4;
            dst[0] = h[0]; dst[1] = h[1]; dst[2] = h[2]; dst[3] = h[3];
        }
    }
    __syncthreads();

    const __half2* spC = sp + (size_t)t * SPH;          // route t
    const __half2* spD = sp + (size_t)(512 + t) * SPH;  // route 512+t

    if (t < 32) Vsh[t] = 0.f;
    __syncthreads();

    for (int it = 0; it < NITERS; it++) {
        float p0, p1, p2, p3;
        if (it == 0) {
            p0 = p1 = p2 = p3 = 1.0f / (float)NROUTES;
        } else {
            float l0 = 0.f, l1 = 0.f, l2 = 0.f, l3 = 0.f;
#pragma unroll
            for (int j = 0; j < 16; j++) {
                float v0 = Vsh[2 * j], v1 = Vsh[2 * j + 1];
                float2 a  = __half22float2(A[j]);
                float2 bb = __half22float2(B[j]);
                float2 cc = __half22float2(spC[j]);
                float2 dd = __half22float2(spD[j]);
                l0 += a.x  * v0 + a.y  * v1;
                l1 += bb.x * v0 + bb.y * v1;
                l2 += cc.x * v0 + cc.y * v1;
                l3 += dd.x * v0 + dd.y * v1;
            }
            float m = fmaxf(fmaxf(l0, l1), fmaxf(l2, l3));
#pragma unroll
            for (int s = 16; s; s >>= 1) m = fmaxf(m, __shfl_xor_sync(0xffffffffu, m, s));
            if (lane == 0) wred[wid] = m;
            __syncthreads();
            if (wid == 0) {
                float mm = (lane < NWARPS) ? wred[lane] : -3.402823e38f;
#pragma unroll
                for (int s = 16; s; s >>= 1) mm = fmaxf(mm, __shfl_xor_sync(0xffffffffu, mm, s));
                if (lane == 0) scal[0] = mm;
            }
            __syncthreads();
            const float bmax = scal[0];

            float e0 = __expf(l0 - bmax);
            float e1 = __expf(l1 - bmax);
            float e2 = __expf(l2 - bmax);
            float e3 = __expf(l3 - bmax);
            float zs = e0 + e1 + e2 + e3;
#pragma unroll
            for (int s = 16; s; s >>= 1) zs += __shfl_xor_sync(0xffffffffu, zs, s);
            if (lane == 0) wred[wid] = zs;
            __syncthreads();
            if (wid == 0) {
                float zz = (lane < NWARPS) ? wred[lane] : 0.f;
#pragma unroll
                for (int s = 16; s; s >>= 1) zz += __shfl_xor_sync(0xffffffffu, zz, s);
                if (lane == 0) scal[1] = zz;
            }
            __syncthreads();
            const float invZ = 1.0f / scal[1];
            p0 = e0 * invZ; p1 = e1 * invZ; p2 = e2 * invZ; p3 = e3 * invZ;
        }

        // multi-value exchange reduction per 8-chunk
#pragma unroll
        for (int ch = 0; ch < 4; ch++) {
            float v[8];
#pragma unroll
            for (int jj = 0; jj < 4; jj++) {
                int j = ch * 4 + jj;
                float2 a  = __half22float2(A[j]);
                float2 bb = __half22float2(B[j]);
                float2 cc = __half22float2(spC[j]);
                float2 dd = __half22float2(spD[j]);
                v[2 * jj]     = p0 * a.x + p1 * bb.x + p2 * cc.x + p3 * dd.x;
                v[2 * jj + 1] = p0 * a.y + p1 * bb.y + p2 * cc.y + p3 * dd.y;
            }
            {
                bool up = (lane & 16) != 0;
#pragma unroll
                for (int i = 0; i < 4; i++) {
                    float keep = up ? v[i + 4] : v[i];
                    float send = up ? v[i] : v[i + 4];
                    v[i] = keep + __shfl_xor_sync(0xffffffffu, send, 16);
                }
                up = (lane & 8) != 0;
#pragma unroll
                for (int i = 0; i < 2; i++) {
                    float keep = up ? v[i + 2] : v[i];
                    float send = up ? v[i] : v[i + 2];
                    v[i] = keep + __shfl_xor_sync(0xffffffffu, send, 8);
                }
                up = (lane & 4) != 0;
                {
                    float keep = up ? v[1] : v[0];
                    float send = up ? v[0] : v[1];
                    v[0] = keep + __shfl_xor_sync(0xffffffffu, send, 4);
                }
                v[0] += __shfl_xor_sync(0xffffffffu, v[0], 2);
                v[0] += __shfl_xor_sync(0xffffffffu, v[0], 1);
            }
            if ((lane & 3) == 0)
                wvec[wid * 32 + ch * 8 + (lane >> 2)] = v[0];
        }
        __syncthreads();
        if (t < 32) {
            float sv = 0.f;
#pragma unroll
            for (int w = 0; w < NWARPS; w++) sv += wvec[w * 32 + t];
            sred[t] = sv;
        }
        __syncthreads();

        if (t < 32) {
            float nr = 0.f;
#pragma unroll
            for (int o = 0; o < OUTDIM; o++) { float sv = sred[o]; nr += sv * sv; }
            float scale = (nr / (1.0f + nr)) * rsqrtf(nr);
            float v = scale * sred[t];
            Vsh[t] += v;
            if (it == NITERS - 1)
                out[((size_t)b * NCAPS + c) * OUTDIM + t] = v;
        }
        __syncthreads();
    }
}

extern "C" void kernel_launch(void* const* d_in, const int* in_sizes, int n_in,
                              void* d_out, int out_size)
{
    const float* x = (const float*)d_in[0];         // [64, 2048, 16]
    const float* W = (const float*)d_in[1];         // [32, 2048, 16, 32]
    float* out = (float*)d_out;                     // [64, 32, 32]

    cudaFuncSetAttribute(caps_k2_route,
                         cudaFuncAttributeMaxDynamicSharedMemorySize, K2_SMEM_BYTES);

    caps_k1_priors<<<NCAPS * 64, 512>>>(x, W);                  // (c, 32-route block)
    caps_k2_route<<<NCAPS * BATCH, 512, K2_SMEM_BYTES>>>(out);  // (c, bp, b1)
}

// round 16
// speedup vs baseline: 1.0912x; 1.0912x over previous
#include <cuda_runtime.h>
#include <cuda_fp16.h>
#include <cstddef>
#include <cstdint>

#define BATCH   64
#define NCAPS   32
#define NROUTES 2048
#define INDIM   16
#define OUTDIM  32
#define NITERS  3
#define NWARPS  16

typedef unsigned long long u64;
#define FMA2(d, a, b, c) \
    asm("fma.rn.f32x2 %0, %1, %2, %3;" : "=l"(d) : "l"(a), "l"(b), "l"(c))
#define PACKF2(o, lo, hi) \
    asm("mov.b64 %0, {%1, %2};" : "=l"(o) : "f"(lo), "f"(hi))
#define UNPACKF2(lo, hi, in) \
    asm("mov.b64 {%0, %1}, %2;" : "=f"(lo), "=f"(hi) : "l"(in))

__device__ __forceinline__ uint32_t smem_u32(const void* p) {
    uint32_t a;
    asm("{ .reg .u64 t; cvta.to.shared.u64 t, %1; cvt.u32.u64 %0, t; }" : "=r"(a) : "l"(p));
    return a;
}
#define CP_ASYNC16(dst_u32, src) \
    asm volatile("cp.async.cg.shared.global [%0], [%1], 16;" :: "r"(dst_u32), "l"(src) : "memory")
#define CP_COMMIT() asm volatile("cp.async.commit_group;" ::: "memory")
#define CP_WAIT0()  asm volatile("cp.async.wait_group 0;" ::: "memory")

// Global fp16 prior buffer (static device scratch).
// half2 layout: pri[c][bp][n][b1][oh], oh = o/2 (16 half2 per (n,b1))
__device__ __half2 g_pri[(size_t)NCAPS * 32 * NROUTES * 2 * 16];

// ================= K1: priors GEMM (W packed in regs, cp.async x staging) =================
// Grid 1024 = (c, 64-route block). Thread = (route rl=t>>3, col-group og=t&7).
#define K1_XROW  20                        // floats per (b,rl) row (16 + 4 pad)
#define K1_XBUF  (8 * 64 * K1_XROW)        // 10240 floats per buffer
#define K1_SMEM_BYTES (2 * K1_XBUF * 4)    // 81920 (double buffered)

__global__ void __launch_bounds__(512)
caps_k1_priors(const float* __restrict__ x, const float* __restrict__ W)
{
    extern __shared__ float xsh[];   // [2][8 b][64 rl][20]
    const int t  = threadIdx.x;
    const int rl = t >> 3;           // 0..63
    const int og = t & 7;            // 0..7
    const int c  = blockIdx.x >> 5;
    const int r0 = (blockIdx.x & 31) * 64;
    const int n  = r0 + rl;

    // W -> packed register pairs
    u64 wp[32];
    {
        const float4* W4 = reinterpret_cast<const float4*>(W)
                         + ((size_t)(c * NROUTES + n) * INDIM) * 8 + og;
#pragma unroll
        for (int i = 0; i < 16; i++) {
            float4 w = __ldg(W4 + i * 8);
            PACKF2(wp[i * 2],     w.x, w.y);
            PACKF2(wp[i * 2 + 1], w.z, w.w);
        }
    }

    const float4* x4 = reinterpret_cast<const float4*>(x);
    const uint32_t xsh_u = smem_u32(xsh);

    // prologue: stage batch-group 0 into buffer 0 (async)
#pragma unroll
    for (int k = 0; k < 4; k++) {
        int idx = t + k * 512;
        int bl = idx >> 8, rem = idx & 255;
        int rr = rem >> 2, q = rem & 3;
        const float4* src = x4 + ((size_t)bl * NROUTES + r0 + rr) * 4 + q;
        CP_ASYNC16(xsh_u + ((bl * 64 + rr) * K1_XROW + q * 4) * 4, src);
    }
    CP_COMMIT();
    CP_WAIT0();
    __syncthreads();

    for (int g = 0; g < 8; g++) {
        float* buf = xsh + (g & 1) * K1_XBUF;
        const uint32_t nbuf_u = xsh_u + (((g + 1) & 1) * K1_XBUF) * 4;

        // kick off next stage asynchronously (no scoreboard stall)
        if (g + 1 < 8) {
#pragma unroll
            for (int k = 0; k < 4; k++) {
                int idx = t + k * 512;
                int bl = idx >> 8, rem = idx & 255;
                int rr = rem >> 2, q = rem & 3;
                const float4* src = x4 + ((size_t)((g + 1) * 8 + bl) * NROUTES + r0 + rr) * 4 + q;
                CP_ASYNC16(nbuf_u + ((bl * 64 + rr) * K1_XROW + q * 4) * 4, src);
            }
            CP_COMMIT();
        }

        // compute current group while next stage is in flight
#pragma unroll
        for (int bl = 0; bl < 8; bl++) {
            const float* xr = &buf[(bl * 64 + rl) * K1_XROW];
            u64 a01 = 0ull, a23 = 0ull;
#pragma unroll
            for (int q = 0; q < 4; q++) {
                float4 xq = *reinterpret_cast<const float4*>(xr + q * 4);
                u64 xx;
                PACKF2(xx, xq.x, xq.x);
                FMA2(a01, xx, wp[(q * 4 + 0) * 2],     a01);
                FMA2(a23, xx, wp[(q * 4 + 0) * 2 + 1], a23);
                PACKF2(xx, xq.y, xq.y);
                FMA2(a01, xx, wp[(q * 4 + 1) * 2],     a01);
                FMA2(a23, xx, wp[(q * 4 + 1) * 2 + 1], a23);
                PACKF2(xx, xq.z, xq.z);
                FMA2(a01, xx, wp[(q * 4 + 2) * 2],     a01);
                FMA2(a23, xx, wp[(q * 4 + 2) * 2 + 1], a23);
                PACKF2(xx, xq.w, xq.w);
                FMA2(a01, xx, wp[(q * 4 + 3) * 2],     a01);
                FMA2(a23, xx, wp[(q * 4 + 3) * 2 + 1], a23);
            }
            float a0, a1, a2, a3;
            UNPACKF2(a0, a1, a01);
            UNPACKF2(a2, a3, a23);

            const int b = g * 8 + bl;
            size_t off = ((((size_t)c * 32 + (b >> 1)) * NROUTES + n) * 2 + (b & 1)) * 16
                       + og * 2;
            union { __half2 h[2]; uint2 u; } pk;
            pk.h[0] = __floats2half2_rn(a0, a1);
            pk.h[1] = __floats2half2_rn(a2, a3);
            *reinterpret_cast<uint2*>(&g_pri[off]) = pk.u;
        }

        if (g + 1 < 8) CP_WAIT0();
        __syncthreads();
    }
}

// ================= K2: routing (1 batch per CTA, 2 CTAs/SM) — R12 verbatim =================
#define SPH 17
#define K2_SP_HALF2S (1024 * SPH)
#define K2_NSCR (32 + 32 + 16 + NWARPS * 32 + 4)
#define K2_SMEM_BYTES ((K2_SP_HALF2S + K2_NSCR) * 4)   // 72016

__global__ void __launch_bounds__(512, 2)
caps_k2_route(float* __restrict__ out)
{
    extern __shared__ __half2 smh[];
    __half2* sp  = smh;
    float* scr  = reinterpret_cast<float*>(smh + K2_SP_HALF2S);
    float* Vsh  = scr;                       // 32
    float* sred = scr + 32;                  // 32
    float* wred = scr + 64;                  // 16
    float* wvec = scr + 80;                  // 16*32
    float* scal = scr + 80 + NWARPS * 32;    // 4

    const int t    = threadIdx.x;
    const int lane = t & 31;
    const int wid  = t >> 5;
    const int b1   = blockIdx.x & 1;
    const int bp   = (blockIdx.x >> 1) & 31;
    const int c    = blockIdx.x >> 6;
    const int b    = bp * 2 + b1;

    const float4* P4 = reinterpret_cast<const float4*>(
        g_pri + (((size_t)c * 32 + bp) * NROUTES) * 32);

    // ---- pass 1: routes 1024..2047 -> sp rows 0..1023 ----
#pragma unroll 2
    for (int k = 0; k < 8; k++) {
        int idx = t + k * 512;
        int nl = idx >> 2, q = idx & 3;
        float4 v = __ldg(P4 + (size_t)(1024 + nl) * 8 + b1 * 4 + q);
        const __half2* h = reinterpret_cast<const __half2*>(&v);
        __half2* dst = sp + (size_t)nl * SPH + q * 4;
        dst[0] = h[0]; dst[1] = h[1]; dst[2] = h[2]; dst[3] = h[3];
    }
    __syncthreads();

    __half2 A[16], B[16];
    {
        const __half2* pA = sp + (size_t)t * SPH;
        const __half2* pB = sp + (size_t)(512 + t) * SPH;
#pragma unroll
        for (int j = 0; j < 16; j++) { A[j] = pA[j]; B[j] = pB[j]; }
    }
    __syncthreads();

    // ---- pass 2: routes 0..1023 -> sp rows ----
#pragma unroll 2
    for (int k = 0; k < 8; k++) {
        int idx = t + k * 512;
        int nl = idx >> 2, q = idx & 3;
        float4 v = __ldg(P4 + (size_t)nl * 8 + b1 * 4 + q);
        const __half2* h = reinterpret_cast<const __half2*>(&v);
        __half2* dst = sp + (size_t)nl * SPH + q * 4;
        dst[0] = h[0]; dst[1] = h[1]; dst[2] = h[2]; dst[3] = h[3];
    }
    __syncthreads();

    const __half2* spC = sp + (size_t)t * SPH;          // route t
    const __half2* spD = sp + (size_t)(512 + t) * SPH;  // route 512+t

    if (t < 32) Vsh[t] = 0.f;
    __syncthreads();

    for (int it = 0; it < NITERS; it++) {
        float p0, p1, p2, p3;
        if (it == 0) {
            p0 = p1 = p2 = p3 = 1.0f / (float)NROUTES;
        } else {
            float l0 = 0.f, l1 = 0.f, l2 = 0.f, l3 = 0.f;
#pragma unroll
            for (int j = 0; j < 16; j++) {
                float v0 = Vsh[2 * j], v1 = Vsh[2 * j + 1];
                float2 a  = __half22float2(A[j]);
                float2 bb = __half22float2(B[j]);
                float2 cc = __half22float2(spC[j]);
                float2 dd = __half22float2(spD[j]);
                l0 += a.x  * v0 + a.y  * v1;
                l1 += bb.x * v0 + bb.y * v1;
                l2 += cc.x * v0 + cc.y * v1;
                l3 += dd.x * v0 + dd.y * v1;
            }
            float m = fmaxf(fmaxf(l0, l1), fmaxf(l2, l3));
#pragma unroll
            for (int s = 16; s; s >>= 1) m = fmaxf(m, __shfl_xor_sync(0xffffffffu, m, s));
            if (lane == 0) wred[wid] = m;
            __syncthreads();
            if (wid == 0) {
                float mm = (lane < NWARPS) ? wred[lane] : -3.402823e38f;
#pragma unroll
                for (int s = 16; s; s >>= 1) mm = fmaxf(mm, __shfl_xor_sync(0xffffffffu, mm, s));
                if (lane == 0) scal[0] = mm;
            }
            __syncthreads();
            const float bmax = scal[0];

            float e0 = __expf(l0 - bmax);
            float e1 = __expf(l1 - bmax);
            float e2 = __expf(l2 - bmax);
            float e3 = __expf(l3 - bmax);
            float zs = e0 + e1 + e2 + e3;
#pragma unroll
            for (int s = 16; s; s >>= 1) zs += __shfl_xor_sync(0xffffffffu, zs, s);
            if (lane == 0) wred[wid] = zs;
            __syncthreads();
            if (wid == 0) {
                float zz = (lane < NWARPS) ? wred[lane] : 0.f;
#pragma unroll
                for (int s = 16; s; s >>= 1) zz += __shfl_xor_sync(0xffffffffu, zz, s);
                if (lane == 0) scal[1] = zz;
            }
            __syncthreads();
            const float invZ = 1.0f / scal[1];
            p0 = e0 * invZ; p1 = e1 * invZ; p2 = e2 * invZ; p3 = e3 * invZ;
        }

        // multi-value exchange reduction per 8-chunk
#pragma unroll
        for (int ch = 0; ch < 4; ch++) {
            float v[8];
#pragma unroll
            for (int jj = 0; jj < 4; jj++) {
                int j = ch * 4 + jj;
                float2 a  = __half22float2(A[j]);
                float2 bb = __half22float2(B[j]);
                float2 cc = __half22float2(spC[j]);
                float2 dd = __half22float2(spD[j]);
                v[2 * jj]     = p0 * a.x + p1 * bb.x + p2 * cc.x + p3 * dd.x;
                v[2 * jj + 1] = p0 * a.y + p1 * bb.y + p2 * cc.y + p3 * dd.y;
            }
            {
                bool up = (lane & 16) != 0;
#pragma unroll
                for (int i = 0; i < 4; i++) {
                    float keep = up ? v[i + 4] : v[i];
                    float send = up ? v[i] : v[i + 4];
                    v[i] = keep + __shfl_xor_sync(0xffffffffu, send, 16);
                }
                up = (lane & 8) != 0;
#pragma unroll
                for (int i = 0; i < 2; i++) {
                    float keep = up ? v[i + 2] : v[i];
                    float send = up ? v[i] : v[i + 2];
                    v[i] = keep + __shfl_xor_sync(0xffffffffu, send, 8);
                }
                up = (lane & 4) != 0;
                {
                    float keep = up ? v[1] : v[0];
                    float send = up ? v[0] : v[1];
                    v[0] = keep + __shfl_xor_sync(0xffffffffu, send, 4);
                }
                v[0] += __shfl_xor_sync(0xffffffffu, v[0], 2);
                v[0] += __shfl_xor_sync(0xffffffffu, v[0], 1);
            }
            if ((lane & 3) == 0)
                wvec[wid * 32 + ch * 8 + (lane >> 2)] = v[0];
        }
        __syncthreads();
        if (t < 32) {
            float sv = 0.f;
#pragma unroll
            for (int w = 0; w < NWARPS; w++) sv += wvec[w * 32 + t];
            sred[t] = sv;
        }
        __syncthreads();

        if (t < 32) {
            float nr = 0.f;
#pragma unroll
            for (int o = 0; o < OUTDIM; o++) { float sv = sred[o]; nr += sv * sv; }
            float scale = (nr / (1.0f + nr)) * rsqrtf(nr);
            float v = scale * sred[t];
            Vsh[t] += v;
            if (it == NITERS - 1)
                out[((size_t)b * NCAPS + c) * OUTDIM + t] = v;
        }
        __syncthreads();
    }
}

extern "C" void kernel_launch(void* const* d_in, const int* in_sizes, int n_in,
                              void* d_out, int out_size)
{
    const float* x = (const float*)d_in[0];         // [64, 2048, 16]
    const float* W = (const float*)d_in[1];         // [32, 2048, 16, 32]
    float* out = (float*)d_out;                     // [64, 32, 32]

    cudaFuncSetAttribute(caps_k1_priors,
                         cudaFuncAttributeMaxDynamicSharedMemorySize, K1_SMEM_BYTES);
    cudaFuncSetAttribute(caps_k2_route,
                         cudaFuncAttributeMaxDynamicSharedMemorySize, K2_SMEM_BYTES);

    caps_k1_priors<<<NCAPS * 32, 512, K1_SMEM_BYTES>>>(x, W);   // (c, 64-route block)
    caps_k2_route<<<NCAPS * BATCH, 512, K2_SMEM_BYTES>>>(out);  // (c, bp, b1)
}